// round 8
// baseline (speedup 1.0000x reference)
#include <cuda_runtime.h>
#include <cstdint>
#include <cstddef>

// ---------------------------------------------------------------------------
// Covariance:  cov[b] = (X^T X)/N - mu mu^T, packed upper triangle.
// X: [64, 4096, 256] f32 -> out: [64, 32896] f32
// TF32 mma.sync m16n8k8 SYRK, triangle-only:
//   triangle = 80 n-units (64m x 8n) per batch; 16 warp-slots x 5 units each.
//   2 CTAs/batch (grid 128), 8 warps/CTA; warp = 64x40 strip (3 slots straddle
//   a slab boundary -> one extra A-frag reload). acc = 5x4x4 = 80 regs.
//   KC=64 double-buffered stage [64k][256d] @ stride 264 (conflict-free).
//   Staging in two 8-group sub-batches interleaved between k-step halves.
// ---------------------------------------------------------------------------

static constexpr int BATCH  = 64;
static constexpr int NPTS   = 4096;
static constexpr int DIM    = 256;
static constexpr int TRI    = DIM * (DIM + 1) / 2;   // 32896
static constexpr int KC     = 64;
static constexpr int NCHUNK = NPTS / KC;             // 64
static constexpr int SROW   = 264;                   // 264 % 32 == 8
static constexpr int STAGE_F = KC * SROW;            // 16896 floats
static constexpr int SMEM_FLOATS = 2 * STAGE_F + 4 * 256 + 256;
static constexpr int SMEM_BYTES  = SMEM_FLOATS * 4;  // 140288

// slot tables: slot -> (mA, nA0, cntA, mB, nB0); units u<cntA in slab A.
__device__ const int8_t SLOT_MA[16] = {0,0,0,0,0,0,0,1, 1,1,1,1,2,2,2,3};
__device__ const int8_t SLOT_NA[16] = {0,5,10,15,20,25,30,11, 16,21,26,31,20,25,30,27};
__device__ const int8_t SLOT_CA[16] = {5,5,5,5,5,5,2,5, 5,5,5,1,5,5,2,5};
__device__ const int8_t SLOT_MB[16] = {0,0,0,0,0,0,1,0, 0,0,0,2,0,0,3,0};
__device__ const int8_t SLOT_NB[16] = {0,0,0,0,0,0,8,0, 0,0,0,16,0,0,24,0};
// per (h, wid) slot assignment; boundary slots (6,14,11) on distinct SMSPs.
__device__ const int8_t SLOT_OF[2][8] = {
    {0, 6, 2, 4, 8, 10, 12, 14},
    {1, 3, 5, 7, 9, 11, 13, 15}};

#define MMA_TF32(ac, A, b0, b1)                                                 \
    asm volatile(                                                               \
        "mma.sync.aligned.m16n8k8.row.col.f32.tf32.tf32.f32 "                   \
        "{%0,%1,%2,%3}, {%4,%5,%6,%7}, {%8,%9}, {%0,%1,%2,%3};"                 \
        : "+f"((ac)[0]), "+f"((ac)[1]), "+f"((ac)[2]), "+f"((ac)[3])            \
        : "r"((A)[0]), "r"((A)[1]), "r"((A)[2]), "r"((A)[3]),                   \
          "r"(b0), "r"(b1))

static __device__ __forceinline__ uint32_t cvt_rna_tf32(float v) {
    uint32_t r;
    asm("cvt.rna.tf32.f32 %0, %1;" : "=r"(r) : "f"(v));
    return r;
}

// 4 k-steps (kbase .. kbase+3) over this warp's 5 units.
static __device__ __forceinline__ void do_ks4(
    const uint32_t* __restrict__ cur, int kbase,
    const int (&mb4)[5], const int (&nb8)[5],
    float (&acc)[5][4][4], int g, int tig)
{
#pragma unroll
    for (int ks = 0; ks < 4; ++ks) {
        const int k0 = (kbase + ks) * 8;
        const uint32_t* r0p = cur + (k0 + tig) * SROW;
        const uint32_t* r1p = cur + (k0 + tig + 4) * SROW;
        uint32_t af[4][4];
        int mcur = -1;
#pragma unroll
        for (int u = 0; u < 5; ++u) {
            if (mb4[u] != mcur) {
                mcur = mb4[u];
#pragma unroll
                for (int mf = 0; mf < 4; ++mf) {
                    const int m0 = mcur + mf * 16 + g;
                    af[mf][0] = r0p[m0];
                    af[mf][1] = r0p[m0 + 8];
                    af[mf][2] = r1p[m0];
                    af[mf][3] = r1p[m0 + 8];
                }
            }
            const uint32_t b0 = r0p[nb8[u] + g];
            const uint32_t b1 = r1p[nb8[u] + g];
#pragma unroll
            for (int mf = 0; mf < 4; ++mf)
                MMA_TF32(acc[u][mf], af[mf], b0, b1);
        }
    }
}

__global__ void __launch_bounds__(256, 1)
cov_mma_kernel(const float* __restrict__ X, float* __restrict__ out)
{
    extern __shared__ float sm[];
    float* buf0 = sm;
    float* buf1 = sm + STAGE_F;
    float* psum = sm + 2 * STAGE_F;        // [4][256]
    float* csum = psum + 4 * 256;          // [256]

    const int tid  = threadIdx.x;
    const int lane = tid & 31;
    const int wid  = tid >> 5;
    const int b    = blockIdx.x >> 1;
    const int h    = blockIdx.x & 1;
    const int g    = lane >> 2;
    const int tig  = lane & 3;

    // ---- unit assignment ----
    const int slot = SLOT_OF[h][wid];
    int mb4[5], nb8[5];
    {
        const int mA = SLOT_MA[slot], nA = SLOT_NA[slot], cA = SLOT_CA[slot];
        const int mB = SLOT_MB[slot], nB = SLOT_NB[slot];
#pragma unroll
        for (int u = 0; u < 5; ++u) {
            const bool inA = (u < cA);
            mb4[u] = (inA ? mA : mB) * 64;
            nb8[u] = (inA ? (nA + u) : (nB + (u - cA))) * 8;
        }
    }

    // staging: thread t owns float4 lane t within each 4096-float4 chunk
    const float4* gp =
        reinterpret_cast<const float4*>(X + (size_t)b * NPTS * DIM) + tid;
    const int dq    = (tid & 63) * 4;
    const int krow0 = tid >> 6;

    float acc[5][4][4] = {};
    float s4[4] = {0.f, 0.f, 0.f, 0.f};
    float4 v[8];

#define STAGE_GROUP(dst, j) do {                                                \
        uint32_t r0 = cvt_rna_tf32(v[(j) & 7].x), r1 = cvt_rna_tf32(v[(j) & 7].y); \
        uint32_t r2 = cvt_rna_tf32(v[(j) & 7].z), r3 = cvt_rna_tf32(v[(j) & 7].w); \
        s4[0] += __uint_as_float(r0); s4[1] += __uint_as_float(r1);             \
        s4[2] += __uint_as_float(r2); s4[3] += __uint_as_float(r3);             \
        *reinterpret_cast<float4*>(&(dst)[(krow0 + 4 * (j)) * SROW + dq]) =     \
            make_float4(__uint_as_float(r0), __uint_as_float(r1),               \
                        __uint_as_float(r2), __uint_as_float(r3));              \
    } while (0)

    // ---- prologue: stage chunk 0 (both halves) ----
#pragma unroll
    for (int half = 0; half < 2; ++half) {
#pragma unroll
        for (int j = 0; j < 8; ++j) v[j] = gp[(half * 8 + j) * 256];
#pragma unroll
        for (int j = 0; j < 8; ++j) STAGE_GROUP(buf0, half * 8 + j);
    }
    __syncthreads();

#pragma unroll 1
    for (int c = 0; c < NCHUNK; ++c) {
        const bool more = (c + 1 < NCHUNK);
        const uint32_t* cur =
            reinterpret_cast<const uint32_t*>((c & 1) ? buf1 : buf0);
        float* nxt = (c & 1) ? buf0 : buf1;

        if (more) {                     // LDG batch A for chunk c+1
#pragma unroll
            for (int j = 0; j < 8; ++j)
                v[j] = gp[(c + 1) * 4096 + j * 256];
        }

        do_ks4(cur, 0, mb4, nb8, acc, g, tig);   // k rows 0..31

        if (more) {
#pragma unroll
            for (int j = 0; j < 8; ++j) STAGE_GROUP(nxt, j);
#pragma unroll
            for (int j = 0; j < 8; ++j)          // LDG batch B
                v[j] = gp[(c + 1) * 4096 + (8 + j) * 256];
        }

        do_ks4(cur, 4, mb4, nb8, acc, g, tig);   // k rows 32..63

        if (more) {
#pragma unroll
            for (int j = 0; j < 8; ++j) STAGE_GROUP(nxt, 8 + j);
        }
        __syncthreads();
    }

    // ---- column-sum reduction ----
    psum[krow0 * 256 + dq + 0] = s4[0];
    psum[krow0 * 256 + dq + 1] = s4[1];
    psum[krow0 * 256 + dq + 2] = s4[2];
    psum[krow0 * 256 + dq + 3] = s4[3];
    __syncthreads();
    csum[tid] = psum[tid] + psum[256 + tid] + psum[512 + tid] + psum[768 + tid];
    __syncthreads();

    // ---- epilogue: cov = acc/N - mu_d mu_e, packed upper triangle ----
    const float invN = 1.0f / (float)NPTS;
    const size_t outb = (size_t)b * TRI;

#pragma unroll
    for (int u = 0; u < 5; ++u) {
#pragma unroll
        for (int mf = 0; mf < 4; ++mf) {
#pragma unroll
            for (int cc = 0; cc < 4; ++cc) {
                const int d = mb4[u] + mf * 16 + g + (cc >> 1) * 8;
                const int e = nb8[u] + 2 * tig + (cc & 1);
                if (e >= d) {
                    const float mu_d = csum[d] * invN;
                    const float mu_e = csum[e] * invN;
                    const int idx = d * DIM - (d * (d - 1)) / 2 - d + e;
                    out[outb + (size_t)idx] = acc[u][mf][cc] * invN - mu_d * mu_e;
                }
            }
        }
    }
}

extern "C" void kernel_launch(void* const* d_in, const int* in_sizes, int n_in,
                              void* d_out, int out_size)
{
    const float* X = (const float*)d_in[0];
    float* out = (float*)d_out;
    cudaFuncSetAttribute(cov_mma_kernel,
                         cudaFuncAttributeMaxDynamicSharedMemorySize,
                         SMEM_BYTES);
    cov_mma_kernel<<<BATCH * 2, 256, SMEM_BYTES>>>(X, out);
}

// round 9
// speedup vs baseline: 1.0130x; 1.0130x over previous
#include <cuda_runtime.h>
#include <cstdint>
#include <cstddef>

// ---------------------------------------------------------------------------
// Covariance:  cov[b] = (X^T X)/N - mu mu^T, packed upper triangle.
// X: [64, 4096, 256] f32 -> out: [64, 32896] f32
// TF32 mma.sync m16n8k8 SYRK, triangle-only.
//   Unit = 64(m) x 8(n) over one k-step. 80 n-units/batch (j >= 8*mi),
//   2 CTAs/batch by j-parity -> 40 units/CTA. 512 threads = 16 warps,
//   4 warps/SMSP; warps 0-7 own 3 units, 8-15 own 2 -> 10 units/SMSP.
//   MMA floor 1280 cyc per 32k; acc <= 48 regs/warp -> deep pipelining room.
//   KC=64 double-buffered stage [64k][256d] @ stride 264, v[4] sub-batches.
// ---------------------------------------------------------------------------

static constexpr int BATCH  = 64;
static constexpr int NPTS   = 4096;
static constexpr int DIM    = 256;
static constexpr int TRI    = DIM * (DIM + 1) / 2;   // 32896
static constexpr int KC     = 64;
static constexpr int NCHUNK = NPTS / KC;             // 64
static constexpr int SROW   = 264;                   // 264 % 32 == 8 -> conflict-free
static constexpr int STAGE_F = KC * SROW;            // 16896 floats
// smem: buf[2][STAGE_F] | psum[8*256] | csum[256]
static constexpr int SMEM_FLOATS = 2 * STAGE_F + 8 * 256 + 256;
static constexpr int SMEM_BYTES  = SMEM_FLOATS * 4;  // 144384

// per-warp unit tables: (m-slab, j-base); actual j = JB + h (CTA parity).
__device__ const int8_t NU_TAB[16] = {3,3,3,3,3,3,3,3, 2,2,2,2,2,2,2,2};
__device__ const int8_t MS_TAB[16][3] = {
    {0,0,0},{0,0,0},{0,0,0},{0,0,0},{0,0,0},{0,1,1},{1,1,1},{1,1,1},
    {1,1,1},{1,1,1},{2,2,2},{2,2,2},{2,2,2},{2,2,2},{3,3,3},{3,3,3}};
__device__ const int8_t JB_TAB[16][3] = {
    {0,2,4},{6,8,10},{12,14,16},{18,20,22},{24,26,28},{30,8,10},
    {12,14,16},{18,20,22},{24,26,24},{28,30,28},{16,18,16},{20,22,20},
    {24,26,24},{28,30,28},{24,26,24},{28,30,28}};

#define MMA_TF32(ac, A, b0, b1)                                                 \
    asm volatile(                                                               \
        "mma.sync.aligned.m16n8k8.row.col.f32.tf32.tf32.f32 "                   \
        "{%0,%1,%2,%3}, {%4,%5,%6,%7}, {%8,%9}, {%0,%1,%2,%3};"                 \
        : "+f"((ac)[0]), "+f"((ac)[1]), "+f"((ac)[2]), "+f"((ac)[3])            \
        : "r"((A)[0]), "r"((A)[1]), "r"((A)[2]), "r"((A)[3]),                   \
          "r"(b0), "r"(b1))

static __device__ __forceinline__ uint32_t cvt_rna_tf32(float v) {
    uint32_t r;
    asm("cvt.rna.tf32.f32 %0, %1;" : "=r"(r) : "f"(v));
    return r;
}

// 4 k-steps (kbase..kbase+3) over this warp's (up to) 3 units.
static __device__ __forceinline__ void do_ks4(
    const uint32_t* __restrict__ cur, int kbase, int nu,
    const int (&mb)[3], const int (&nb)[3],
    float (&acc)[3][4][4], int g, int tig)
{
#pragma unroll
    for (int ks = 0; ks < 4; ++ks) {
        const int k0 = (kbase + ks) * 8;
        const uint32_t* r0p = cur + (k0 + tig) * SROW;
        const uint32_t* r1p = cur + (k0 + tig + 4) * SROW;
        uint32_t af[4][4];
        int mcur = -1;
#pragma unroll
        for (int u = 0; u < 3; ++u) {
            if (u >= nu) break;
            if (mb[u] != mcur) {
                mcur = mb[u];
#pragma unroll
                for (int mf = 0; mf < 4; ++mf) {
                    const int m0 = mcur + mf * 16 + g;
                    af[mf][0] = r0p[m0];
                    af[mf][1] = r0p[m0 + 8];
                    af[mf][2] = r1p[m0];
                    af[mf][3] = r1p[m0 + 8];
                }
            }
            const uint32_t b0 = r0p[nb[u] + g];
            const uint32_t b1 = r1p[nb[u] + g];
#pragma unroll
            for (int mf = 0; mf < 4; ++mf)
                MMA_TF32(acc[u][mf], af[mf], b0, b1);
        }
    }
}

__global__ void __launch_bounds__(512, 1)
cov_mma_kernel(const float* __restrict__ X, float* __restrict__ out)
{
    extern __shared__ float sm[];
    float* buf0 = sm;
    float* buf1 = sm + STAGE_F;
    float* psum = sm + 2 * STAGE_F;        // [8][256]
    float* csum = psum + 8 * 256;          // [256]

    const int tid  = threadIdx.x;
    const int lane = tid & 31;
    const int wid  = tid >> 5;
    const int b    = blockIdx.x >> 1;
    const int h    = blockIdx.x & 1;
    const int g    = lane >> 2;
    const int tig  = lane & 3;

    // ---- unit assignment from tables ----
    const int nu = NU_TAB[wid];
    int mb[3], nb[3];
#pragma unroll
    for (int u = 0; u < 3; ++u) {
        mb[u] = (int)MS_TAB[wid][u] * 64;
        nb[u] = ((int)JB_TAB[wid][u] + h) * 8;
    }

    // staging: thread t owns float4 lane (t & 511); rows (t>>6) + 8j
    const float4* gp =
        reinterpret_cast<const float4*>(X + (size_t)b * NPTS * DIM) + tid;
    const int dq    = (tid & 63) * 4;
    const int krow0 = tid >> 6;            // 0..7

    float acc[3][4][4] = {};
    float s4[4] = {0.f, 0.f, 0.f, 0.f};
    float4 v[4];

#define STAGE_GROUP(dst, j) do {                                                \
        uint32_t r0 = cvt_rna_tf32(v[(j) & 3].x), r1 = cvt_rna_tf32(v[(j) & 3].y); \
        uint32_t r2 = cvt_rna_tf32(v[(j) & 3].z), r3 = cvt_rna_tf32(v[(j) & 3].w); \
        s4[0] += __uint_as_float(r0); s4[1] += __uint_as_float(r1);             \
        s4[2] += __uint_as_float(r2); s4[3] += __uint_as_float(r3);             \
        *reinterpret_cast<float4*>(&(dst)[(krow0 + 8 * (j)) * SROW + dq]) =     \
            make_float4(__uint_as_float(r0), __uint_as_float(r1),               \
                        __uint_as_float(r2), __uint_as_float(r3));              \
    } while (0)

    // ---- prologue: stage chunk 0 ----
#pragma unroll
    for (int half = 0; half < 2; ++half) {
#pragma unroll
        for (int j = 0; j < 4; ++j) v[j] = gp[(half * 4 + j) * 512];
#pragma unroll
        for (int j = 0; j < 4; ++j) STAGE_GROUP(buf0, half * 4 + j);
    }
    __syncthreads();

#pragma unroll 1
    for (int c = 0; c < NCHUNK; ++c) {
        const bool more = (c + 1 < NCHUNK);
        const uint32_t* cur =
            reinterpret_cast<const uint32_t*>((c & 1) ? buf1 : buf0);
        float* nxt = (c & 1) ? buf0 : buf1;

        if (more) {                     // LDG batch A (k rows 0..31 of c+1)
#pragma unroll
            for (int j = 0; j < 4; ++j)
                v[j] = gp[(c + 1) * 4096 + j * 512];
        }

        do_ks4(cur, 0, nu, mb, nb, acc, g, tig);     // k rows 0..31

        if (more) {
#pragma unroll
            for (int j = 0; j < 4; ++j) STAGE_GROUP(nxt, j);
#pragma unroll
            for (int j = 0; j < 4; ++j)              // LDG batch B
                v[j] = gp[(c + 1) * 4096 + (4 + j) * 512];
        }

        do_ks4(cur, 4, nu, mb, nb, acc, g, tig);     // k rows 32..63

        if (more) {
#pragma unroll
            for (int j = 0; j < 4; ++j) STAGE_GROUP(nxt, 4 + j);
        }
        __syncthreads();
    }

    // ---- column-sum reduction ----
    psum[krow0 * 256 + dq + 0] = s4[0];
    psum[krow0 * 256 + dq + 1] = s4[1];
    psum[krow0 * 256 + dq + 2] = s4[2];
    psum[krow0 * 256 + dq + 3] = s4[3];
    __syncthreads();
    if (tid < 256) {
        float t = 0.f;
#pragma unroll
        for (int r = 0; r < 8; ++r) t += psum[r * 256 + tid];
        csum[tid] = t;
    }
    __syncthreads();

    // ---- epilogue: cov = acc/N - mu_d mu_e, packed upper triangle ----
    const float invN = 1.0f / (float)NPTS;
    const size_t outb = (size_t)b * TRI;

#pragma unroll
    for (int u = 0; u < 3; ++u) {
        if (u >= nu) break;
#pragma unroll
        for (int mf = 0; mf < 4; ++mf) {
#pragma unroll
            for (int cc = 0; cc < 4; ++cc) {
                const int d = mb[u] + mf * 16 + g + (cc >> 1) * 8;
                const int e = nb[u] + 2 * tig + (cc & 1);
                if (e >= d) {
                    const float mu_d = csum[d] * invN;
                    const float mu_e = csum[e] * invN;
                    const int idx = d * DIM - (d * (d - 1)) / 2 - d + e;
                    out[outb + (size_t)idx] = acc[u][mf][cc] * invN - mu_d * mu_e;
                }
            }
        }
    }
}

extern "C" void kernel_launch(void* const* d_in, const int* in_sizes, int n_in,
                              void* d_out, int out_size)
{
    const float* X = (const float*)d_in[0];
    float* out = (float*)d_out;
    cudaFuncSetAttribute(cov_mma_kernel,
                         cudaFuncAttributeMaxDynamicSharedMemorySize,
                         SMEM_BYTES);
    cov_mma_kernel<<<BATCH * 2, 512, SMEM_BYTES>>>(X, out);
}